// round 5
// baseline (speedup 1.0000x reference)
#include <cuda_runtime.h>
#include <cstdint>

#define NCH 8
#define HW 512
#define IMG (HW*HW)
#define CROP 506
#define CIMG (CROP*CROP)
#define NSHIFT 81

// 12 nonzero taps of the 13-tap half-pixel kernel, offsets -6..+5
__constant__ float c_w12[12] = {
    -1.20162964e-4f,  1.615524292e-3f, -1.0385513306e-2f,  4.3619155884e-2f,
    -1.45397186478e-1f, 6.1066818237e-1f, 6.1066818237e-1f, -1.45397186478e-1f,
     4.3619155884e-2f, -1.0385513306e-2f, 1.615524292e-3f, -1.20162964e-4f };

// device scratch (static: allocation is forbidden)
__device__ float g_tmp [NCH*IMG];
__device__ float g_p   [NCH*IMG];
__device__ float g_p2e [NCH*IMG];
__device__ float g_p2s [NCH*IMG];
__device__ float g_p2se[NCH*IMG];
__device__ float g_ap  [NCH*CIMG];
__device__ float g_sii [NCH*CIMG];
__device__ float g_kx  [NCH*41];
__device__ float g_ky  [NCH*41];
__device__ double g_rho[NSHIFT*NCH];

__global__ void k_zero() {
    int t = blockIdx.x*blockDim.x + threadIdx.x;
    if (t < NSHIFT*NCH) g_rho[t] = 0.0;
}

// exact separable factors of the rank-1 Gaussian MTF kernel
__global__ void k_sepfac(const float* __restrict__ K) {
    int c = blockIdx.x; int t = threadIdx.x;
    __shared__ float cm[41];
    __shared__ float tot;
    const float* Kc = K + c*1681;
    if (t < 41) { float s = 0.f; for (int y = 0; y < 41; ++y) s += Kc[y*41+t]; cm[t] = s; }
    __syncthreads();
    if (t == 0) { float s = 0.f; for (int i = 0; i < 41; ++i) s += cm[i]; tot = s; }
    __syncthreads();
    if (t < 41) {
        g_kx[c*41+t] = cm[t];
        float r = 0.f; for (int x = 0; x < 41; ++x) r += Kc[t*41+x];
        g_ky[c*41+t] = r / tot;
    }
}

// 41-tap horizontal Gaussian with edge clamp, 8 outputs/thread
__global__ void k_gaussH(const float* __restrict__ pan) {
    int i = blockIdx.x*blockDim.x + threadIdx.x;
    if (i >= NCH*512*64) return;
    int c = i >> 15; int rem = i & 32767;
    int y = rem >> 6; int x0 = (rem & 63) << 3;
    const float* row = pan + c*IMG + (y<<9);
    const float* w = g_kx + c*41;
    float v[48];
#pragma unroll
    for (int t = 0; t < 48; ++t) { int xx = x0 + t - 20; xx = min(511, max(0, xx)); v[t] = row[xx]; }
    float s[8];
#pragma unroll
    for (int j = 0; j < 8; ++j) s[j] = 0.f;
#pragma unroll
    for (int t = 0; t < 41; ++t) {
        float wt = w[t];
#pragma unroll
        for (int j = 0; j < 8; ++j) s[j] += wt * v[t+j];
    }
    float* o = g_tmp + c*IMG + (y<<9) + x0;
#pragma unroll
    for (int j = 0; j < 8; ++j) o[j] = s[j];
}

// 41-tap vertical Gaussian with edge clamp
__global__ void k_gaussV() {
    int i = blockIdx.x*blockDim.x + threadIdx.x;
    if (i >= NCH*512*64) return;
    int c = i >> 15; int rem = i & 32767;
    int yg = rem >> 9; int x = rem & 511;
    int y0 = yg << 3;
    const float* col = g_tmp + c*IMG + x;
    const float* w = g_ky + c*41;
    float v[48];
#pragma unroll
    for (int t = 0; t < 48; ++t) { int yy = y0 + t - 20; yy = min(511, max(0, yy)); v[t] = col[yy<<9]; }
    float s[8];
#pragma unroll
    for (int j = 0; j < 8; ++j) s[j] = 0.f;
#pragma unroll
    for (int t = 0; t < 41; ++t) {
        float wt = w[t];
#pragma unroll
        for (int j = 0; j < 8; ++j) s[j] += wt * v[t+j];
    }
    float* o = g_p + c*IMG + (y0<<9) + x;
#pragma unroll
    for (int j = 0; j < 8; ++j) o[j<<9] = s[j];
}

// 12-tap half-pixel filter, SAME zero-pad, horizontal: g_p -> g_p2e
__global__ void k_c13h(int which) {
    const float* in = g_p; float* out = g_p2e; (void)which;
    int i = blockIdx.x*blockDim.x + threadIdx.x;
    if (i >= NCH*512*64) return;
    int c = i >> 15; int rem = i & 32767;
    int y = rem >> 6; int x0 = (rem & 63) << 3;
    const float* row = in + c*IMG + (y<<9);
    float v[19];
#pragma unroll
    for (int t = 0; t < 19; ++t) { int xx = x0 + t - 6; v[t] = ((unsigned)xx < 512u) ? row[xx] : 0.f; }
    float s[8];
#pragma unroll
    for (int j = 0; j < 8; ++j) s[j] = 0.f;
#pragma unroll
    for (int t = 0; t < 12; ++t) {
        float wt = c_w12[t];
#pragma unroll
        for (int j = 0; j < 8; ++j) s[j] += wt * v[t+j];
    }
    float* o = out + c*IMG + (y<<9) + x0;
#pragma unroll
    for (int j = 0; j < 8; ++j) o[j] = s[j];
}

// vertical variant. which: 0 = g_p->g_p2s, 1 = g_p2e->g_p2se
__global__ void k_c13v(int which) {
    const float* in = which ? g_p2e : g_p;
    float* out = which ? g_p2se : g_p2s;
    int i = blockIdx.x*blockDim.x + threadIdx.x;
    if (i >= NCH*512*64) return;
    int c = i >> 15; int rem = i & 32767;
    int yg = rem >> 9; int x = rem & 511;
    int y0 = yg << 3;
    const float* col = in + c*IMG + x;
    float v[19];
#pragma unroll
    for (int t = 0; t < 19; ++t) { int yy = y0 + t - 6; v[t] = ((unsigned)yy < 512u) ? col[yy<<9] : 0.f; }
    float s[8];
#pragma unroll
    for (int j = 0; j < 8; ++j) s[j] = 0.f;
#pragma unroll
    for (int t = 0; t < 12; ++t) {
        float wt = c_w12[t];
#pragma unroll
        for (int j = 0; j < 8; ++j) s[j] += wt * v[t+j];
    }
    float* o = out + c*IMG + (y0<<9) + x;
#pragma unroll
    for (int j = 0; j < 8; ++j) o[j<<9] = s[j];
}

// ms-side precompute: box window offsets -7..+8, zero pad outside 506x506
__global__ void k_ahsum(const float* __restrict__ ms) {
    int x = blockIdx.x*blockDim.x + threadIdx.x;
    if (x >= CROP) return;
    int y = blockIdx.y, c = blockIdx.z;
    const float* row = ms + c*IMG + (y+3)*512 + 3;
    float s = 0.f;
    for (int dx = -7; dx <= 8; ++dx) { int xx = x + dx; if ((unsigned)xx < (unsigned)CROP) s += row[xx]; }
    g_tmp[c*IMG + y*CROP + x] = s;
}
__global__ void k_aprime(const float* __restrict__ ms) {
    int x = blockIdx.x*blockDim.x + threadIdx.x;
    if (x >= CROP) return;
    int y = blockIdx.y, c = blockIdx.z;
    float s = 0.f;
    for (int dy = -7; dy <= 8; ++dy) { int yy = y + dy; if ((unsigned)yy < (unsigned)CROP) s += g_tmp[c*IMG + yy*CROP + x]; }
    float a = ms[c*IMG + (y+3)*512 + (x+3)];
    g_ap[c*CIMG + y*CROP + x] = a - s * (1.0f/256.0f);
}
__global__ void k_sqh() {
    int x = blockIdx.x*blockDim.x + threadIdx.x;
    if (x >= CROP) return;
    int y = blockIdx.y, c = blockIdx.z;
    const float* row = g_ap + c*CIMG + y*CROP;
    float s = 0.f;
    for (int dx = -7; dx <= 8; ++dx) { int xx = x + dx; if ((unsigned)xx < (unsigned)CROP) { float v = row[xx]; s += v*v; } }
    g_tmp[c*IMG + y*CROP + x] = s;
}
__global__ void k_sii() {
    int x = blockIdx.x*blockDim.x + threadIdx.x;
    if (x >= CROP) return;
    int y = blockIdx.y, c = blockIdx.z;
    float s = 0.f;
    for (int dy = -7; dy <= 8; ++dy) { int yy = y + dy; if ((unsigned)yy < (unsigned)CROP) s += g_tmp[c*IMG + yy*CROP + x]; }
    g_sii[c*CIMG + y*CROP + x] = fmaxf(s, 1e-20f);
}

// ---------------- fused rho kernel: one CTA = (shift, channel, 64x32 tile) ----------------
// output tile: 64 cols (x) x 32 rows (y)
// smem (14486 floats = 57.9 KB -> 3 CTAs/SM):
//   A [0,5828):        sb 62x94 (stride 94)          -> later sa 47x80 + start of h2/h3
//   B [5828,10726):    hb 62x79 (stride 79)          -> later rest of h2/h3
//     (h2 47x65 at [3760,6815), h3 47x65 at [6815,9870))
//   C [10726,14486):   sbp 47x80 (b')                -> later red[16]
#define A_OFF 0
#define B_OFF 5828
#define C_OFF 10726
#define SMEM_FLOATS 14486
#define SB_STR 94
#define HB_STR 79
#define P_STR 80
#define Q_STR 65
#define H2_OFF 3760
#define H3_OFF 6815

__global__ void __launch_bounds__(512, 3)
k_rho()
{
    extern __shared__ float sm[];
    float* sb  = sm + A_OFF;
    float* hb  = sm + B_OFF;
    float* sbp = sm + C_OFF;
    float* sa  = sm + A_OFF;            // overlay after phase 2 (47x80)
    float* h2  = sm + H2_OFF;           // overlay after phase 2 (47x65)
    float* h3  = sm + H3_OFF;           // overlay after phase 2 (47x65)
    float* red = sm + C_OFF;            // overlay after phase 3

    const int z = blockIdx.z;
    const int s = z >> 3, c = z & 7;
    const int mi = s / 9, ni = s - mi*9;
    const int ri = (mi >> 1) - 2, ci = (ni >> 1) - 2;
    const int pk = ((mi & 1) << 1) | (ni & 1);
    const float* p2k = (pk == 0) ? g_p : (pk == 1) ? g_p2e : (pk == 2) ? g_p2s : g_p2se;
    const int y0 = (int)(blockIdx.y) << 5, x0 = (int)(blockIdx.x) << 6;
    const int tid = threadIdx.x;
    const int offy = 3 - ri, offx = 3 - ci;
    const float* p2c = p2k + c*IMG;
    const float* apc = g_ap + c*CIMG;

    // phase 0: load b 62x94 (zero outside crop)
    for (int k = tid; k < 62*94; k += 512) {
        int i = k / 94, j = k - i*94;
        int gy = y0 - 14 + i, gx = x0 - 14 + j;
        float v = 0.f;
        if ((unsigned)gy < (unsigned)CROP && (unsigned)gx < (unsigned)CROP)
            v = p2c[(gy + offy)*512 + (gx + offx)];
        sb[i*SB_STR + j] = v;
    }
    __syncthreads();

    // phase 1: horizontal 16-sums of b -> hb[62][79]; 62x8 = 496 units (chunk 10)
    if (tid < 62*8) {
        int i = tid >> 3, ch = tid & 7;
        int u0 = ch*10, u1 = min(u0 + 10, 79);
        const float* r = sb + i*SB_STR;
        float ssum = 0.f;
#pragma unroll
        for (int t = 0; t < 16; ++t) ssum += r[u0 + t];
        float* hrow = hb + i*HB_STR;
        hrow[u0] = ssum;
        for (int u = u0 + 1; u < u1; ++u) { ssum += r[u+15] - r[u-1]; hrow[u] = ssum; }
    }
    __syncthreads();

    // phase 2: b' = b - box16(b)/256 on 47x79; 79x4 = 316 units (chunk 12 rows)
    if (tid < 79*4) {
        int u = tid % 79, seg = tid / 79;
        int v0 = seg*12, v1 = min(v0 + 12, 47);
        float ssum = 0.f;
#pragma unroll
        for (int t = 0; t < 16; ++t) ssum += hb[(v0 + t)*HB_STR + u];
        for (int v = v0; v < v1; ++v) {
            if (v > v0) ssum += hb[(v+15)*HB_STR + u] - hb[(v-1)*HB_STR + u];
            float bp = 0.f;
            int gy = y0 - 7 + v, gx = x0 - 7 + u;
            if ((unsigned)gy < (unsigned)CROP && (unsigned)gx < (unsigned)CROP)
                bp = sb[(v+7)*SB_STR + (u+7)] - ssum * (1.0f/256.0f);
            sbp[v*P_STR + u] = bp;
        }
    }
    __syncthreads();

    // phase 2.5: load a' 47x79 into sa (overlays dead sb)
    for (int k = tid; k < 47*79; k += 512) {
        int i = k / 79, j = k - i*79;
        int gy = y0 - 7 + i, gx = x0 - 7 + j;
        sa[i*P_STR + j] = ((unsigned)gy < (unsigned)CROP && (unsigned)gx < (unsigned)CROP)
                          ? apc[gy*CROP + gx] : 0.f;
    }
    __syncthreads();

    // phase 3: horizontal 16-sums of b'^2 and a'b' -> h2/h3 47x64; 47x4 = 188 units (chunk 16)
    if (tid < 47*4) {
        int v = tid >> 2, ch = tid & 3;
        int q0 = ch << 4;
        const float* bpr = sbp + v*P_STR;
        const float* ar  = sa  + v*P_STR;
        float s2 = 0.f, s3 = 0.f;
#pragma unroll
        for (int t = 0; t < 16; ++t) { float b_ = bpr[q0+t], a_ = ar[q0+t]; s2 += b_*b_; s3 += a_*b_; }
        float* h2r = h2 + v*Q_STR; float* h3r = h3 + v*Q_STR;
        h2r[q0] = s2; h3r[q0] = s3;
#pragma unroll
        for (int q = q0 + 1; q < q0 + 16; ++q) {
            float nb = bpr[q+15], ob = bpr[q-1];
            float na = ar[q+15],  oa = ar[q-1];
            s2 += nb*nb - ob*ob;
            s3 += na*nb - oa*ob;
            h2r[q] = s2; h3r[q] = s3;
        }
    }
    __syncthreads();

    // phase 4: vertical 16-sums -> rho; 64 cols x 4 segs (8 rows each) = 256 units
    float acc = 0.f;
    const float* siic = g_sii + c*CIMG;
    if (tid < 256) {
        int q = tid & 63, seg = tid >> 6;
        int p0 = seg << 3;
        float s2 = 0.f, s3 = 0.f;
#pragma unroll
        for (int t = 0; t < 16; ++t) { s2 += h2[(p0+t)*Q_STR + q]; s3 += h3[(p0+t)*Q_STR + q]; }
#pragma unroll
        for (int p = p0; p < p0 + 8; ++p) {
            if (p > p0) {
                s2 += h2[(p+15)*Q_STR + q] - h2[(p-1)*Q_STR + q];
                s3 += h3[(p+15)*Q_STR + q] - h3[(p-1)*Q_STR + q];
            }
            int gy = y0 + p, gx = x0 + q;
            if (gy < CROP && gx < CROP) {
                float sjj = fmaxf(s2, 1e-20f);
                float den = sqrtf(siic[gy*CROP + gx] * sjj) + 1e-20f;
                acc += __fdividef(s3, den);
            }
        }
    }
    __syncthreads();

    // reduce 512 threads -> one double atomic
#pragma unroll
    for (int o = 16; o > 0; o >>= 1) acc += __shfl_down_sync(0xffffffffu, acc, o);
    if ((tid & 31) == 0) red[tid >> 5] = acc;
    __syncthreads();
    if (tid < 16) {
        float v = red[tid];
#pragma unroll
        for (int o = 8; o > 0; o >>= 1) v += __shfl_down_sync(0xffffu, v, o, 16);
        if (tid == 0) atomicAdd(&g_rho[z], (double)v);
    }
}

__global__ void k_argmax(int* __restrict__ out) {
    int c = threadIdx.x;
    if (c >= NCH) return;
    double best = -1e300; int bi = 0;
    for (int s = 0; s < NSHIFT; ++s) {
        double v = g_rho[s*NCH + c];
        if (v > best) { best = v; bi = s; }
    }
    out[c]       = bi / 9 - 4;
    out[NCH + c] = bi % 9 - 4;
}

extern "C" void kernel_launch(void* const* d_in, const int* in_sizes, int n_in,
                              void* d_out, int out_size) {
    const float* ms  = (const float*)d_in[0];
    const float* pan = (const float*)d_in[1];
    const float* mtf = (const float*)d_in[2];
    int* out = (int*)d_out;
    (void)in_sizes; (void)n_in; (void)out_size;

    cudaFuncSetAttribute(k_rho, cudaFuncAttributeMaxDynamicSharedMemorySize,
                         SMEM_FLOATS * (int)sizeof(float));

    k_zero<<<1, 656>>>();
    k_sepfac<<<NCH, 64>>>(mtf);
    k_gaussH<<<1024, 256>>>(pan);
    k_gaussV<<<1024, 256>>>();
    k_c13h<<<1024, 256>>>(0);
    k_c13v<<<1024, 256>>>(0);
    k_c13v<<<1024, 256>>>(1);

    dim3 mb(128), mg((CROP + 127)/128, CROP, NCH);
    k_ahsum <<<mg, mb>>>(ms);
    k_aprime<<<mg, mb>>>(ms);
    k_sqh   <<<mg, mb>>>();
    k_sii   <<<mg, mb>>>();

    // 8 x-tiles (64 wide), 16 y-tiles (32 tall), 648 (shift,channel) pairs
    k_rho<<<dim3(8, 16, NSHIFT*NCH), 512, SMEM_FLOATS * (int)sizeof(float)>>>();
    k_argmax<<<1, 32>>>(out);
}

// round 6
// speedup vs baseline: 1.7709x; 1.7709x over previous
#include <cuda_runtime.h>
#include <cstdint>

#define NCH 8
#define HW 512
#define IMG (HW*HW)
#define CROP 506
#define CIMG (CROP*CROP)
#define NSHIFT 81

// 12 nonzero taps of the 13-tap half-pixel kernel, offsets -6..+5
__constant__ float c_w12[12] = {
    -1.20162964e-4f,  1.615524292e-3f, -1.0385513306e-2f,  4.3619155884e-2f,
    -1.45397186478e-1f, 6.1066818237e-1f, 6.1066818237e-1f, -1.45397186478e-1f,
     4.3619155884e-2f, -1.0385513306e-2f, 1.615524292e-3f, -1.20162964e-4f };

// device scratch (static: allocation is forbidden)
__device__ float g_tmp [NCH*IMG];
__device__ float g_p   [NCH*IMG];
__device__ float g_p2e [NCH*IMG];
__device__ float g_p2s [NCH*IMG];
__device__ float g_p2se[NCH*IMG];
__device__ float g_ap  [NCH*CIMG];
__device__ float g_sii [NCH*CIMG];
__device__ float g_kx  [NCH*41];
__device__ float g_ky  [NCH*41];
__device__ double g_rho[NSHIFT*NCH];

__global__ void k_zero() {
    int t = blockIdx.x*blockDim.x + threadIdx.x;
    if (t < NSHIFT*NCH) g_rho[t] = 0.0;
}

// exact separable factors of the rank-1 Gaussian MTF kernel
__global__ void k_sepfac(const float* __restrict__ K) {
    int c = blockIdx.x; int t = threadIdx.x;
    __shared__ float cm[41];
    __shared__ float tot;
    const float* Kc = K + c*1681;
    if (t < 41) { float s = 0.f; for (int y = 0; y < 41; ++y) s += Kc[y*41+t]; cm[t] = s; }
    __syncthreads();
    if (t == 0) { float s = 0.f; for (int i = 0; i < 41; ++i) s += cm[i]; tot = s; }
    __syncthreads();
    if (t < 41) {
        g_kx[c*41+t] = cm[t];
        float r = 0.f; for (int x = 0; x < 41; ++x) r += Kc[t*41+x];
        g_ky[c*41+t] = r / tot;
    }
}

// 41-tap horizontal Gaussian with edge clamp, 8 outputs/thread
__global__ void k_gaussH(const float* __restrict__ pan) {
    int i = blockIdx.x*blockDim.x + threadIdx.x;
    if (i >= NCH*512*64) return;
    int c = i >> 15; int rem = i & 32767;
    int y = rem >> 6; int x0 = (rem & 63) << 3;
    const float* row = pan + c*IMG + (y<<9);
    const float* w = g_kx + c*41;
    float v[48];
#pragma unroll
    for (int t = 0; t < 48; ++t) { int xx = x0 + t - 20; xx = min(511, max(0, xx)); v[t] = row[xx]; }
    float s[8];
#pragma unroll
    for (int j = 0; j < 8; ++j) s[j] = 0.f;
#pragma unroll
    for (int t = 0; t < 41; ++t) {
        float wt = w[t];
#pragma unroll
        for (int j = 0; j < 8; ++j) s[j] += wt * v[t+j];
    }
    float* o = g_tmp + c*IMG + (y<<9) + x0;
#pragma unroll
    for (int j = 0; j < 8; ++j) o[j] = s[j];
}

// 41-tap vertical Gaussian with edge clamp
__global__ void k_gaussV() {
    int i = blockIdx.x*blockDim.x + threadIdx.x;
    if (i >= NCH*512*64) return;
    int c = i >> 15; int rem = i & 32767;
    int yg = rem >> 9; int x = rem & 511;
    int y0 = yg << 3;
    const float* col = g_tmp + c*IMG + x;
    const float* w = g_ky + c*41;
    float v[48];
#pragma unroll
    for (int t = 0; t < 48; ++t) { int yy = y0 + t - 20; yy = min(511, max(0, yy)); v[t] = col[yy<<9]; }
    float s[8];
#pragma unroll
    for (int j = 0; j < 8; ++j) s[j] = 0.f;
#pragma unroll
    for (int t = 0; t < 41; ++t) {
        float wt = w[t];
#pragma unroll
        for (int j = 0; j < 8; ++j) s[j] += wt * v[t+j];
    }
    float* o = g_p + c*IMG + (y0<<9) + x;
#pragma unroll
    for (int j = 0; j < 8; ++j) o[j<<9] = s[j];
}

// 12-tap half-pixel filter, SAME zero-pad, horizontal: g_p -> g_p2e
__global__ void k_c13h(int which) {
    const float* in = g_p; float* out = g_p2e; (void)which;
    int i = blockIdx.x*blockDim.x + threadIdx.x;
    if (i >= NCH*512*64) return;
    int c = i >> 15; int rem = i & 32767;
    int y = rem >> 6; int x0 = (rem & 63) << 3;
    const float* row = in + c*IMG + (y<<9);
    float v[19];
#pragma unroll
    for (int t = 0; t < 19; ++t) { int xx = x0 + t - 6; v[t] = ((unsigned)xx < 512u) ? row[xx] : 0.f; }
    float s[8];
#pragma unroll
    for (int j = 0; j < 8; ++j) s[j] = 0.f;
#pragma unroll
    for (int t = 0; t < 12; ++t) {
        float wt = c_w12[t];
#pragma unroll
        for (int j = 0; j < 8; ++j) s[j] += wt * v[t+j];
    }
    float* o = out + c*IMG + (y<<9) + x0;
#pragma unroll
    for (int j = 0; j < 8; ++j) o[j] = s[j];
}

// vertical variant. which: 0 = g_p->g_p2s, 1 = g_p2e->g_p2se
__global__ void k_c13v(int which) {
    const float* in = which ? g_p2e : g_p;
    float* out = which ? g_p2se : g_p2s;
    int i = blockIdx.x*blockDim.x + threadIdx.x;
    if (i >= NCH*512*64) return;
    int c = i >> 15; int rem = i & 32767;
    int yg = rem >> 9; int x = rem & 511;
    int y0 = yg << 3;
    const float* col = in + c*IMG + x;
    float v[19];
#pragma unroll
    for (int t = 0; t < 19; ++t) { int yy = y0 + t - 6; v[t] = ((unsigned)yy < 512u) ? col[yy<<9] : 0.f; }
    float s[8];
#pragma unroll
    for (int j = 0; j < 8; ++j) s[j] = 0.f;
#pragma unroll
    for (int t = 0; t < 12; ++t) {
        float wt = c_w12[t];
#pragma unroll
        for (int j = 0; j < 8; ++j) s[j] += wt * v[t+j];
    }
    float* o = out + c*IMG + (y0<<9) + x;
#pragma unroll
    for (int j = 0; j < 8; ++j) o[j<<9] = s[j];
}

// ---- ms-side precompute with sliding windows (box window offsets -7..+8, zero pad) ----
// horizontal box of ms crop: thread = (row, 8-px segment)
__global__ void k_ahsum(const float* __restrict__ ms) {
    int seg = threadIdx.x;             // 0..63
    int y = blockIdx.x, c = blockIdx.y;
    int x0 = seg << 3;
    if (x0 >= CROP) return;
    const float* row = ms + c*IMG + (y+3)*512 + 3;
    float* o = g_tmp + c*IMG + y*CROP;
    float s = 0.f;
    for (int dx = -7; dx <= 8; ++dx) { int xx = x0 + dx; if ((unsigned)xx < (unsigned)CROP) s += row[xx]; }
    o[x0] = s;
    int x1 = min(x0 + 8, CROP);
    for (int x = x0 + 1; x < x1; ++x) {
        int xa = x + 8, xr = x - 8;
        if (xa < CROP) s += row[xa];
        if (xr >= 0)   s -= row[xr];
        o[x] = s;
    }
}
// vertical box of g_tmp + subtract: thread = (col, 8-row segment)
__global__ void k_aprime(const float* __restrict__ ms) {
    int x = blockIdx.x*blockDim.x + threadIdx.x;
    if (x >= CROP) return;
    int yseg = blockIdx.y, c = blockIdx.z;
    int y0 = yseg << 3;
    if (y0 >= CROP) return;
    const float* col = g_tmp + c*IMG;
    float s = 0.f;
    for (int dy = -7; dy <= 8; ++dy) { int yy = y0 + dy; if ((unsigned)yy < (unsigned)CROP) s += col[yy*CROP + x]; }
    int y1 = min(y0 + 8, CROP);
    for (int y = y0; y < y1; ++y) {
        if (y > y0) {
            int ya = y + 8, yr = y - 8;
            if (ya < CROP) s += col[ya*CROP + x];
            if (yr >= 0)   s -= col[yr*CROP + x];
        }
        float a = ms[c*IMG + (y+3)*512 + (x+3)];
        g_ap[c*CIMG + y*CROP + x] = a - s * (1.0f/256.0f);
    }
}
// horizontal box of a'^2
__global__ void k_sqh() {
    int seg = threadIdx.x;
    int y = blockIdx.x, c = blockIdx.y;
    int x0 = seg << 3;
    if (x0 >= CROP) return;
    const float* row = g_ap + c*CIMG + y*CROP;
    float* o = g_tmp + c*IMG + y*CROP;
    float s = 0.f;
    for (int dx = -7; dx <= 8; ++dx) { int xx = x0 + dx; if ((unsigned)xx < (unsigned)CROP) { float v = row[xx]; s += v*v; } }
    o[x0] = s;
    int x1 = min(x0 + 8, CROP);
    for (int x = x0 + 1; x < x1; ++x) {
        int xa = x + 8, xr = x - 8;
        if (xa < CROP) { float v = row[xa]; s += v*v; }
        if (xr >= 0)   { float v = row[xr]; s -= v*v; }
        o[x] = s;
    }
}
// vertical box -> sii
__global__ void k_sii() {
    int x = blockIdx.x*blockDim.x + threadIdx.x;
    if (x >= CROP) return;
    int yseg = blockIdx.y, c = blockIdx.z;
    int y0 = yseg << 3;
    if (y0 >= CROP) return;
    const float* col = g_tmp + c*IMG;
    float s = 0.f;
    for (int dy = -7; dy <= 8; ++dy) { int yy = y0 + dy; if ((unsigned)yy < (unsigned)CROP) s += col[yy*CROP + x]; }
    int y1 = min(y0 + 8, CROP);
    for (int y = y0; y < y1; ++y) {
        if (y > y0) {
            int ya = y + 8, yr = y - 8;
            if (ya < CROP) s += col[ya*CROP + x];
            if (yr >= 0)   s -= col[yr*CROP + x];
        }
        g_sii[c*CIMG + y*CROP + x] = fmaxf(s, 1e-20f);
    }
}

// ---------------- fused rho kernel: one CTA = (shift, channel, 64x64 tile) ----------------
// smem layout (22943 floats = 91.8 KB -> 2 CTAs/SM):
//   A [0,8930):      sb 94x95 (b tile)           -> later sa 79x81 (a')
//   B [8930,16544):  hb 94x81 (hsum16 of b)      -> later h2 48x65 | h3 48x65 (half-tiles)
//   C [16544,22943): sbp 79x81 (b')              -> later red[16]
#define A_OFF 0
#define B_OFF 8930
#define C_OFF 16544
#define SMEM_FLOATS 22943
#define BSTR 95
#define HSTR 81
#define PSTR 81
#define QSTR 65

__global__ void __launch_bounds__(512, 2)
k_rho()
{
    extern __shared__ float sm[];
    float* sb  = sm + A_OFF;
    float* hb  = sm + B_OFF;
    float* sbp = sm + C_OFF;
    float* sa  = sm + A_OFF;            // overlay after phase 2
    float* h2  = sm + B_OFF;            // overlay: 48x65 per half
    float* h3  = sm + B_OFF + 48*QSTR;
    float* red = sm + C_OFF;            // overlay after final phase

    const int z = blockIdx.z;
    const int s = z >> 3, c = z & 7;
    const int mi = s / 9, ni = s - mi*9;
    const int ri = (mi >> 1) - 2, ci = (ni >> 1) - 2;
    const int pk = ((mi & 1) << 1) | (ni & 1);
    const float* p2k = (pk == 0) ? g_p : (pk == 1) ? g_p2e : (pk == 2) ? g_p2s : g_p2se;
    const int y0 = (int)(blockIdx.y) << 6, x0 = (int)(blockIdx.x) << 6;
    const int tid = threadIdx.x;
    const int offy = 3 - ri, offx = 3 - ci;
    const float* p2c = p2k + c*IMG;
    const float* apc = g_ap + c*CIMG;

    // prefetch a' into registers (independent of phases 0-2; hides global latency)
    float apre[13];
#pragma unroll
    for (int r = 0; r < 13; ++r) {
        int k = tid + (r << 9);
        float v = 0.f;
        if (k < 79*79) {
            int i = k / 79, j = k - i*79;
            int gy = y0 - 7 + i, gx = x0 - 7 + j;
            if ((unsigned)gy < (unsigned)CROP && (unsigned)gx < (unsigned)CROP)
                v = apc[gy*CROP + gx];
        }
        apre[r] = v;
    }

    // phase 0: load b 94x94 (zero outside crop)
    for (int k = tid; k < 94*94; k += 512) {
        int i = k / 94, j = k - i*94;
        int gy = y0 - 14 + i, gx = x0 - 14 + j;
        float v = 0.f;
        if ((unsigned)gy < (unsigned)CROP && (unsigned)gx < (unsigned)CROP)
            v = p2c[(gy + offy)*512 + (gx + offx)];
        sb[i*BSTR + j] = v;
    }
    __syncthreads();

    // phase 1: horizontal 16-sums of b -> hb[94][79]; 94x6 = 564 units (chunk 13/14)
    for (int un = tid; un < 94*6; un += 512) {
        int i = un / 6, ch = un - i*6;
        int u0 = ch*13, u1 = (ch == 5) ? 79 : u0 + 13;
        const float* r = sb + i*BSTR;
        float ssum = 0.f;
#pragma unroll
        for (int t = 0; t < 16; ++t) ssum += r[u0 + t];
        float* hrow = hb + i*HSTR;
        hrow[u0] = ssum;
        for (int u = u0 + 1; u < u1; ++u) { ssum += r[u+15] - r[u-1]; hrow[u] = ssum; }
    }
    __syncthreads();

    // phase 2: b' = b - box16(b)/256 on 79x79; 79x6 = 474 units single pass (rows 14/13)
    if (tid < 79*6) {
        int u = tid % 79, seg = tid / 79;
        int v0 = (seg == 0) ? 0 : 13*seg + 1;
        int v1 = (seg == 0) ? 14 : v0 + 13;
        float ssum = 0.f;
#pragma unroll
        for (int t = 0; t < 16; ++t) ssum += hb[(v0 + t)*HSTR + u];
        for (int v = v0; v < v1; ++v) {
            if (v > v0) ssum += hb[(v+15)*HSTR + u] - hb[(v-1)*HSTR + u];
            float bp = 0.f;
            int gy = y0 - 7 + v, gx = x0 - 7 + u;
            if ((unsigned)gy < (unsigned)CROP && (unsigned)gx < (unsigned)CROP)
                bp = sb[(v+7)*BSTR + (u+7)] - ssum * (1.0f/256.0f);
            sbp[v*PSTR + u] = bp;
        }
    }
    __syncthreads();

    // phase 2.5: store prefetched a' into sa (overlays dead sb) — STS only
#pragma unroll
    for (int r = 0; r < 13; ++r) {
        int k = tid + (r << 9);
        if (k < 79*79) {
            int i = k / 79, j = k - i*79;
            sa[i*PSTR + j] = apre[r];
        }
    }
    __syncthreads();

    float acc = 0.f;
    const float* siic = g_sii + c*CIMG;
#pragma unroll
    for (int half = 0; half < 2; ++half) {
        const int vbase = half << 5;
        // phase 3: hsum16 of b'^2, a'b' -> h2/h3[48][64]; 48x10 = 480 units, single pass
        if (tid < 480) {
            int vr = tid / 10, ch = tid - (tid/10)*10;
            int v = vbase + vr;
            if (v <= 78) {
                int q0 = (ch < 4) ? ch*7 : 28 + (ch-4)*6;
                int qw = (ch < 4) ? 7 : 6;
                const float* bpr = sbp + v*PSTR;
                const float* ar  = sa  + v*PSTR;
                float s2 = 0.f, s3 = 0.f;
#pragma unroll
                for (int t = 0; t < 16; ++t) { float b_ = bpr[q0+t], a_ = ar[q0+t]; s2 += b_*b_; s3 += a_*b_; }
                float* h2r = h2 + vr*QSTR; float* h3r = h3 + vr*QSTR;
                h2r[q0] = s2; h3r[q0] = s3;
                for (int q = q0 + 1; q < q0 + qw; ++q) {
                    float nb = bpr[q+15], ob = bpr[q-1];
                    float na = ar[q+15],  oa = ar[q-1];
                    s2 += nb*nb - ob*ob;
                    s3 += na*nb - oa*ob;
                    h2r[q] = s2; h3r[q] = s3;
                }
            }
        }
        __syncthreads();

        // phase 4: vertical 16-sums -> rho for rows p = vbase + seg*4 .. +3 (all 512 threads)
        {
            int q = tid & 63, seg = tid >> 6;
            int pr0 = seg << 2;
            float s2 = 0.f, s3 = 0.f;
#pragma unroll
            for (int t = 0; t < 16; ++t) { s2 += h2[(pr0+t)*QSTR + q]; s3 += h3[(pr0+t)*QSTR + q]; }
#pragma unroll
            for (int pr = pr0; pr < pr0 + 4; ++pr) {
                if (pr > pr0) {
                    s2 += h2[(pr+15)*QSTR + q] - h2[(pr-1)*QSTR + q];
                    s3 += h3[(pr+15)*QSTR + q] - h3[(pr-1)*QSTR + q];
                }
                int gy = y0 + vbase + pr, gx = x0 + q;
                if (gy < CROP && gx < CROP) {
                    float sjj = fmaxf(s2, 1e-20f);
                    float den = sqrtf(siic[gy*CROP + gx] * sjj) + 1e-20f;
                    acc += __fdividef(s3, den);
                }
            }
        }
        __syncthreads();
    }

    // reduce 512 threads -> one double atomic
#pragma unroll
    for (int o = 16; o > 0; o >>= 1) acc += __shfl_down_sync(0xffffffffu, acc, o);
    if ((tid & 31) == 0) red[tid >> 5] = acc;
    __syncthreads();
    if (tid < 16) {
        float v = red[tid];
#pragma unroll
        for (int o = 8; o > 0; o >>= 1) v += __shfl_down_sync(0xffffu, v, o, 16);
        if (tid == 0) atomicAdd(&g_rho[z], (double)v);
    }
}

__global__ void k_argmax(int* __restrict__ out) {
    int c = threadIdx.x;
    if (c >= NCH) return;
    double best = -1e300; int bi = 0;
    for (int s = 0; s < NSHIFT; ++s) {
        double v = g_rho[s*NCH + c];
        if (v > best) { best = v; bi = s; }
    }
    out[c]       = bi / 9 - 4;
    out[NCH + c] = bi % 9 - 4;
}

extern "C" void kernel_launch(void* const* d_in, const int* in_sizes, int n_in,
                              void* d_out, int out_size) {
    const float* ms  = (const float*)d_in[0];
    const float* pan = (const float*)d_in[1];
    const float* mtf = (const float*)d_in[2];
    int* out = (int*)d_out;
    (void)in_sizes; (void)n_in; (void)out_size;

    cudaFuncSetAttribute(k_rho, cudaFuncAttributeMaxDynamicSharedMemorySize,
                         SMEM_FLOATS * (int)sizeof(float));

    k_zero<<<1, 656>>>();
    k_sepfac<<<NCH, 64>>>(mtf);
    k_gaussH<<<1024, 256>>>(pan);
    k_gaussV<<<1024, 256>>>();
    k_c13h<<<1024, 256>>>(0);
    k_c13v<<<1024, 256>>>(0);
    k_c13v<<<1024, 256>>>(1);

    // ms-side precompute (sliding-window versions)
    k_ahsum <<<dim3(CROP, NCH), 64>>>(ms);
    k_aprime<<<dim3(4, 64, NCH), 128>>>(ms);
    k_sqh   <<<dim3(CROP, NCH), 64>>>();
    k_sii   <<<dim3(4, 64, NCH), 128>>>();

    k_rho<<<dim3(8, 8, NSHIFT*NCH), 512, SMEM_FLOATS * (int)sizeof(float)>>>();
    k_argmax<<<1, 32>>>(out);
}